// round 6
// baseline (speedup 1.0000x reference)
#include <cuda_runtime.h>

// (B, N, T, H) = (16, 256, 96, 128)
#define BB 16
#define NN 256
#define TT 96
#define HH 128
#define EPS 1e-5f
#define G  2            // (b,n) pairs per block in the main kernel

// Scratch (static __device__ — allocation-free)
__device__ float g_C[TT * HH];       // time_emb @ W3            (48 KB)
__device__ float g_nodeS[NN * HH];   // node_emb @ W2            (128 KB)
__device__ float g_Wf[TT * HH];      // Wp @ W1  (fused proj)    (48 KB)
__device__ float g_bias[HH];         // bp @ W1 + bf

// 16-lane-group f32 sum: 4-round shfl butterfly (offsets 1..8 stay inside
// each 16-lane half). redux.sync.add.f32 is NOT available on sm_103a.
__device__ __forceinline__ float group16_sum(float v) {
#pragma unroll
    for (int off = 1; off < 16; off <<= 1)
        v += __shfl_xor_sync(0xffffffffu, v, off);
    return v;
}

// ---------------------------------------------------------------------------
// Prep kernel: all the tiny GEMMs. 449 blocks x 512 threads, 4-way split-K.
// ---------------------------------------------------------------------------
__global__ __launch_bounds__(512) void prep_kernel(
    const float* __restrict__ Wp,
    const float* __restrict__ bp,
    const float* __restrict__ Wf,
    const float* __restrict__ bf,
    const float* __restrict__ node_emb,
    const float* __restrict__ time_emb) {

    __shared__ float vsh[HH];
    __shared__ float partial[4][HH];

    const int r = blockIdx.x;
    const int k = threadIdx.x & (HH - 1);
    const int p = threadIdx.x >> 7;       // 0..3

    const float* __restrict__ v;
    const float* __restrict__ W;
    if (r < TT)                { v = time_emb + r * HH;        W = Wf + 2 * HH * HH; }
    else if (r < 2 * TT)       { v = Wp + (r - TT) * HH;       W = Wf; }
    else if (r < 2 * TT + NN)  { v = node_emb + (r - 2*TT)*HH; W = Wf + HH * HH; }
    else                       { v = bp;                       W = Wf; }

    if (threadIdx.x < HH) vsh[threadIdx.x] = v[threadIdx.x];
    __syncthreads();

    float acc = 0.f;
    const int h0 = p * 32;
#pragma unroll
    for (int hh = 0; hh < 32; hh++) {
        const int h = h0 + hh;
        acc += vsh[h] * W[h * HH + k];   // coalesced over k
    }
    partial[p][k] = acc;
    __syncthreads();

    if (threadIdx.x < HH) {
        float s = partial[0][k] + partial[1][k] + partial[2][k] + partial[3][k];
        if (r < TT)               g_C[r * HH + k] = s;
        else if (r < 2 * TT)      g_Wf[(r - TT) * HH + k] = s;
        else if (r < 2 * TT + NN) g_nodeS[(r - 2 * TT) * HH + k] = s;
        else                      g_bias[k] = s + bf[k];
    }
}

// ---------------------------------------------------------------------------
// Main kernel: 2048 blocks x 256 threads; block handles G=2 (b,n) pairs.
// Phase 1: As[g,k] = bias[k] + nodeS[n,k] + sum_t xs[g,t] * Wfused[t,k]
//          (256 outputs, exactly 1 per thread, 96 FMA)
// Phase 2: 16 lanes per row, 2 rows per warp per pass. Lane il owns cols
//   {4il..+4} and {64+4il..+4}. Software-pipelined C loads (next pass's
//   LDGs issued before this pass's shfl chain). gamma/beta re-read from
//   smem each pass (trades 16 persistent regs for 4 LDS.128) so the kernel
//   fits 5 CTAs/SM. Row mean/var via 4-round shfl butterfly.
// ---------------------------------------------------------------------------
__global__ __launch_bounds__(256, 5) void gpe_main_kernel(
    const float* __restrict__ x,
    const float* __restrict__ gamma,
    const float* __restrict__ beta,
    float* __restrict__ out) {

    __shared__ float xs[G * TT];
    __shared__ float As[G * HH];
    __shared__ float gs[HH];
    __shared__ float bs[HH];

    const int tid   = threadIdx.x;
    const int pair0 = blockIdx.x * G;

    if (tid < G * TT) xs[tid] = x[(size_t)pair0 * TT + tid];
    if (tid >= 128)   { gs[tid - 128] = gamma[tid - 128]; }
    else              { bs[tid]       = beta[tid]; }
    __syncthreads();

    // Phase 1: 256 outputs, 1 per thread, 96 FMA each
    {
        const int g = tid >> 7;
        const int k = tid & (HH - 1);
        const int n = (pair0 + g) & (NN - 1);
        float acc = __ldg(g_bias + k) + __ldg(g_nodeS + n * HH + k);
        const float* __restrict__ xg = xs + g * TT;
#pragma unroll 8
        for (int t = 0; t < TT; t++)
            acc += xg[t] * g_Wf[t * HH + k];
        As[tid] = acc;
    }
    __syncthreads();

    // Phase 2
    const int w    = tid >> 5;
    const int l    = tid & 31;
    const int rgrp = l >> 4;          // which of the 2 rows this pass
    const int il   = l & 15;
    const int col0 = 4 * il;          // second chunk at col0 + 64
    const int r0   = w * 2 + rgrp;    // base row; passes add 16

#pragma unroll 1
    for (int g = 0; g < G; g++) {
        // A slice for this pair, register-resident across all 96 rows
        const float4 a0 = *reinterpret_cast<const float4*>(As + g * HH + col0);
        const float4 a1 = *reinterpret_cast<const float4*>(As + g * HH + 64 + col0);
        float* __restrict__ obase = out + ((size_t)(pair0 + g) * TT) * HH;

        // prime the pipeline
        const float* __restrict__ crow0 = g_C + r0 * HH;
        float4 c0 = __ldg(reinterpret_cast<const float4*>(crow0 + col0));
        float4 c1 = __ldg(reinterpret_cast<const float4*>(crow0 + 64 + col0));

#pragma unroll
        for (int pass = 0; pass < 6; pass++) {
            const int row = pass * 16 + r0;

            // prefetch next pass's C before the dependent shfl chain
            float4 n0, n1;
            if (pass < 5) {
                const float* __restrict__ crn = g_C + (row + 16) * HH;
                n0 = __ldg(reinterpret_cast<const float4*>(crn + col0));
                n1 = __ldg(reinterpret_cast<const float4*>(crn + 64 + col0));
            }

            float4 v0, v1;
            v0.x = fmaxf(a0.x + c0.x, 0.f);
            v0.y = fmaxf(a0.y + c0.y, 0.f);
            v0.z = fmaxf(a0.z + c0.z, 0.f);
            v0.w = fmaxf(a0.w + c0.w, 0.f);
            v1.x = fmaxf(a1.x + c1.x, 0.f);
            v1.y = fmaxf(a1.y + c1.y, 0.f);
            v1.z = fmaxf(a1.z + c1.z, 0.f);
            v1.w = fmaxf(a1.w + c1.w, 0.f);

            float s1 = v0.x + v0.y + v0.z + v0.w
                     + v1.x + v1.y + v1.z + v1.w;
            float s2 = v0.x * v0.x + v0.y * v0.y + v0.z * v0.z + v0.w * v0.w
                     + v1.x * v1.x + v1.y * v1.y + v1.z * v1.z + v1.w * v1.w;

            s1 = group16_sum(s1);
            s2 = group16_sum(s2);

            const float mean = s1 * (1.f / HH);
            const float var  = s2 * (1.f / HH) - mean * mean;
            const float rstd = rsqrtf(var + EPS);

            // gamma/beta from smem (transient)
            const float4 gg0 = *reinterpret_cast<const float4*>(gs + col0);
            const float4 gg1 = *reinterpret_cast<const float4*>(gs + 64 + col0);
            const float4 bb0 = *reinterpret_cast<const float4*>(bs + col0);
            const float4 bb1 = *reinterpret_cast<const float4*>(bs + 64 + col0);

            float4 o0, o1;
            o0.x = (v0.x - mean) * rstd * gg0.x + bb0.x;
            o0.y = (v0.y - mean) * rstd * gg0.y + bb0.y;
            o0.z = (v0.z - mean) * rstd * gg0.z + bb0.z;
            o0.w = (v0.w - mean) * rstd * gg0.w + bb0.w;
            o1.x = (v1.x - mean) * rstd * gg1.x + bb1.x;
            o1.y = (v1.y - mean) * rstd * gg1.y + bb1.y;
            o1.z = (v1.z - mean) * rstd * gg1.z + bb1.z;
            o1.w = (v1.w - mean) * rstd * gg1.w + bb1.w;

            float* __restrict__ orow = obase + row * HH;
            __stcs(reinterpret_cast<float4*>(orow + col0), o0);
            __stcs(reinterpret_cast<float4*>(orow + 64 + col0), o1);

            c0 = n0;
            c1 = n1;
        }
    }
}

// ---------------------------------------------------------------------------
// Inputs: 0:x 1:Wp 2:bp 3:Wf 4:bf 5:gamma 6:beta 7:node_emb 8:time_emb
// ---------------------------------------------------------------------------
extern "C" void kernel_launch(void* const* d_in, const int* in_sizes, int n_in,
                              void* d_out, int out_size) {
    const float* x        = (const float*)d_in[0];
    const float* Wp       = (const float*)d_in[1];
    const float* bp       = (const float*)d_in[2];
    const float* Wf       = (const float*)d_in[3];
    const float* bf       = (const float*)d_in[4];
    const float* gamma    = (const float*)d_in[5];
    const float* beta     = (const float*)d_in[6];
    const float* node_emb = (const float*)d_in[7];
    const float* time_emb = (const float*)d_in[8];
    float* out = (float*)d_out;

    prep_kernel<<<2 * TT + NN + 1, 512>>>(Wp, bp, Wf, bf, node_emb, time_emb);
    gpe_main_kernel<<<(BB * NN) / G, 256>>>(x, gamma, beta, out);
}

// round 8
// speedup vs baseline: 1.1251x; 1.1251x over previous
#include <cuda_runtime.h>
#include <cstdint>

// (B, N, T, H) = (16, 256, 96, 128)
#define BB 16
#define NN 256
#define TT 96
#define HH 128
#define EPS 1e-5f

#define CHUNK_ROWS  32
#define NUM_CHUNKS  (TT / CHUNK_ROWS)              // 3
#define CHUNK_BYTES (CHUNK_ROWS * HH * 4)          // 16384
#define DYN_SMEM    (2 * CHUNK_ROWS * HH * 4)      // 32 KB (double buffer)

// Scratch (static __device__ — allocation-free)
__device__ float g_C[TT * HH];       // time_emb @ W3            (48 KB)
__device__ float g_nodeS[NN * HH];   // node_emb @ W2            (128 KB)
__device__ float g_Wf[TT * HH];      // Wp @ W1  (fused proj)    (48 KB)
__device__ float g_bias[HH];         // bp @ W1 + bf

// 16-lane-group f32 sum: 4-round shfl butterfly (offsets 1..8 stay inside
// each 16-lane half). redux.sync.add.f32 is NOT available on sm_103a.
__device__ __forceinline__ float group16_sum(float v) {
#pragma unroll
    for (int off = 1; off < 16; off <<= 1)
        v += __shfl_xor_sync(0xffffffffu, v, off);
    return v;
}

// ---------------------------------------------------------------------------
// Prep kernel: all the tiny GEMMs. 449 blocks x 512 threads, 4-way split-K.
// ---------------------------------------------------------------------------
__global__ __launch_bounds__(512) void prep_kernel(
    const float* __restrict__ Wp,
    const float* __restrict__ bp,
    const float* __restrict__ Wf,
    const float* __restrict__ bf,
    const float* __restrict__ node_emb,
    const float* __restrict__ time_emb) {

    __shared__ float vsh[HH];
    __shared__ float partial[4][HH];

    const int r = blockIdx.x;
    const int k = threadIdx.x & (HH - 1);
    const int p = threadIdx.x >> 7;       // 0..3

    const float* __restrict__ v;
    const float* __restrict__ W;
    if (r < TT)                { v = time_emb + r * HH;        W = Wf + 2 * HH * HH; }
    else if (r < 2 * TT)       { v = Wp + (r - TT) * HH;       W = Wf; }
    else if (r < 2 * TT + NN)  { v = node_emb + (r - 2*TT)*HH; W = Wf + HH * HH; }
    else                       { v = bp;                       W = Wf; }

    if (threadIdx.x < HH) vsh[threadIdx.x] = v[threadIdx.x];
    __syncthreads();

    float acc = 0.f;
    const int h0 = p * 32;
#pragma unroll
    for (int hh = 0; hh < 32; hh++) {
        const int h = h0 + hh;
        acc += vsh[h] * W[h * HH + k];   // coalesced over k
    }
    partial[p][k] = acc;
    __syncthreads();

    if (threadIdx.x < HH) {
        float s = partial[0][k] + partial[1][k] + partial[2][k] + partial[3][k];
        if (r < TT)               g_C[r * HH + k] = s;
        else if (r < 2 * TT)      g_Wf[(r - TT) * HH + k] = s;
        else if (r < 2 * TT + NN) g_nodeS[(r - 2 * TT) * HH + k] = s;
        else                      g_bias[k] = s + bf[k];
    }
}

// ---------------------------------------------------------------------------
// Main kernel: 4096 blocks x 256 threads; block handles ONE (b,n) pair.
// Phase 1: As[k] = bias[k] + nodeS[n,k] + sum_t xs[t] * Wfused[t,k]
//          (split-K=2 across the two thread halves, smem combine)
// Phase 2/3 pipelined over 3 chunks of 32 rows:
//   compute chunk c into smem buffer (c&1) with conflict-free STS.128, then
//   ONE cp.async.bulk (shared->global, 16 KB contiguous) drains it while the
//   next chunk computes into the other buffer. wait_group 1 gates buffer
//   reuse; wait_group 0 before exit. No STG in the hot path — the TMA
//   engine does all global writes in perfect 128B bursts.
// ---------------------------------------------------------------------------
__global__ __launch_bounds__(256, 5) void gpe_main_kernel(
    const float* __restrict__ x,
    const float* __restrict__ gamma,
    const float* __restrict__ beta,
    float* __restrict__ out) {

    extern __shared__ float buf[];        // 2 x 32 x 128 floats = 32 KB
    __shared__ float xs[TT];
    __shared__ float partial[2][HH];
    __shared__ float As[HH];
    __shared__ float gs[HH];
    __shared__ float bs[HH];

    const int pair = blockIdx.x;
    const int n    = pair & (NN - 1);
    const int tid  = threadIdx.x;

    if (tid < TT) xs[tid] = x[(size_t)pair * TT + tid];
    if (tid < HH) gs[tid] = gamma[tid];
    else          bs[tid - HH] = beta[tid - HH];
    __syncthreads();

    // Phase 1: split-K=2 (48 FMA per thread), combine in smem
    {
        const int k  = tid & (HH - 1);
        const int p  = tid >> 7;
        const int t0 = p * 48;
        float acc = 0.f;
#pragma unroll 8
        for (int tt = 0; tt < 48; tt++)
            acc += xs[t0 + tt] * g_Wf[(t0 + tt) * HH + k];
        partial[p][k] = acc;
    }
    __syncthreads();
    if (tid < HH)
        As[tid] = __ldg(g_bias + tid) + __ldg(g_nodeS + n * HH + tid)
                + partial[0][tid] + partial[1][tid];
    __syncthreads();

    // Phase 2/3
    const int w    = tid >> 5;
    const int l    = tid & 31;
    const int rgrp = l >> 4;
    const int il   = l & 15;
    const int col0 = 4 * il;

    const float4 a0  = *reinterpret_cast<const float4*>(As + col0);
    const float4 a1  = *reinterpret_cast<const float4*>(As + 64 + col0);
    const float4 gg0 = *reinterpret_cast<const float4*>(gs + col0);
    const float4 gg1 = *reinterpret_cast<const float4*>(gs + 64 + col0);
    const float4 bb0 = *reinterpret_cast<const float4*>(bs + col0);
    const float4 bb1 = *reinterpret_cast<const float4*>(bs + 64 + col0);

#pragma unroll
    for (int c = 0; c < NUM_CHUNKS; c++) {
        // recycle buffer (c&1): its previous bulk store must have drained
        if (c >= 2) {
            if (tid == 0)
                asm volatile("cp.async.bulk.wait_group 1;" ::: "memory");
            __syncthreads();
        }
        float* __restrict__ cbuf = buf + (c & 1) * (CHUNK_ROWS * HH);

#pragma unroll
        for (int p = 0; p < 2; p++) {
            const int lrow = p * 16 + w * 2 + rgrp;    // 0..31
            const int row  = c * CHUNK_ROWS + lrow;
            const float* __restrict__ crow = g_C + row * HH;
            const float4 c0 = __ldg(reinterpret_cast<const float4*>(crow + col0));
            const float4 c1 = __ldg(reinterpret_cast<const float4*>(crow + 64 + col0));

            float4 v0, v1;
            v0.x = fmaxf(a0.x + c0.x, 0.f);
            v0.y = fmaxf(a0.y + c0.y, 0.f);
            v0.z = fmaxf(a0.z + c0.z, 0.f);
            v0.w = fmaxf(a0.w + c0.w, 0.f);
            v1.x = fmaxf(a1.x + c1.x, 0.f);
            v1.y = fmaxf(a1.y + c1.y, 0.f);
            v1.z = fmaxf(a1.z + c1.z, 0.f);
            v1.w = fmaxf(a1.w + c1.w, 0.f);

            float s1 = v0.x + v0.y + v0.z + v0.w
                     + v1.x + v1.y + v1.z + v1.w;
            float s2 = v0.x * v0.x + v0.y * v0.y + v0.z * v0.z + v0.w * v0.w
                     + v1.x * v1.x + v1.y * v1.y + v1.z * v1.z + v1.w * v1.w;

            s1 = group16_sum(s1);
            s2 = group16_sum(s2);

            const float mean = s1 * (1.f / HH);
            const float var  = s2 * (1.f / HH) - mean * mean;
            const float rstd = rsqrtf(var + EPS);

            float4 o0, o1;
            o0.x = (v0.x - mean) * rstd * gg0.x + bb0.x;
            o0.y = (v0.y - mean) * rstd * gg0.y + bb0.y;
            o0.z = (v0.z - mean) * rstd * gg0.z + bb0.z;
            o0.w = (v0.w - mean) * rstd * gg0.w + bb0.w;
            o1.x = (v1.x - mean) * rstd * gg1.x + bb1.x;
            o1.y = (v1.y - mean) * rstd * gg1.y + bb1.y;
            o1.z = (v1.z - mean) * rstd * gg1.z + bb1.z;
            o1.w = (v1.w - mean) * rstd * gg1.w + bb1.w;

            float* __restrict__ brow = cbuf + lrow * HH;
            *reinterpret_cast<float4*>(brow + col0)      = o0;
            *reinterpret_cast<float4*>(brow + 64 + col0) = o1;
        }
        __syncthreads();

        if (tid == 0) {
            float* dst = out + (size_t)pair * (TT * HH) + c * (CHUNK_ROWS * HH);
            uint32_t sbuf = (uint32_t)__cvta_generic_to_shared(cbuf);
            asm volatile("fence.proxy.async.shared::cta;" ::: "memory");
            asm volatile(
                "cp.async.bulk.global.shared::cta.bulk_group [%0], [%1], %2;"
                :: "l"(dst), "r"(sbuf), "n"(CHUNK_BYTES) : "memory");
            asm volatile("cp.async.bulk.commit_group;" ::: "memory");
        }
        // no sync needed here: next chunk writes the OTHER buffer
    }

    // drain all pending bulk stores before the CTA exits
    if (tid == 0)
        asm volatile("cp.async.bulk.wait_group 0;" ::: "memory");
}

// ---------------------------------------------------------------------------
// Inputs: 0:x 1:Wp 2:bp 3:Wf 4:bf 5:gamma 6:beta 7:node_emb 8:time_emb
// ---------------------------------------------------------------------------
extern "C" void kernel_launch(void* const* d_in, const int* in_sizes, int n_in,
                              void* d_out, int out_size) {
    const float* x        = (const float*)d_in[0];
    const float* Wp       = (const float*)d_in[1];
    const float* bp       = (const float*)d_in[2];
    const float* Wf       = (const float*)d_in[3];
    const float* bf       = (const float*)d_in[4];
    const float* gamma    = (const float*)d_in[5];
    const float* beta     = (const float*)d_in[6];
    const float* node_emb = (const float*)d_in[7];
    const float* time_emb = (const float*)d_in[8];
    float* out = (float*)d_out;

    prep_kernel<<<2 * TT + NN + 1, 512>>>(Wp, bp, Wf, bf, node_emb, time_emb);
    gpe_main_kernel<<<BB * NN, 256, DYN_SMEM>>>(x, gamma, beta, out);
}

// round 9
// speedup vs baseline: 1.3263x; 1.1789x over previous
#include <cuda_runtime.h>
#include <cstdint>

// (B, N, T, H) = (16, 256, 96, 128)
#define BB 16
#define NN 256
#define TT 96
#define HH 128
#define EPS 1e-5f
#define NPAIR (BB * NN)        // 4096

// Scratch (static __device__ — allocation-free)
__device__ float g_C[TT * HH];        // time_emb @ W3            (48 KB)
__device__ float g_nodeS[NN * HH];    // node_emb @ W2            (128 KB)
__device__ float g_Wf[TT * HH];       // Wp @ W1  (fused proj)    (48 KB)
__device__ float g_bias[HH];          // bp @ W1 + bf
__device__ float g_A[NPAIR * HH];     // per-pair row: x@Wf + bias + nodeS (2 MB)

// 16-lane-group f32 sum: 4-round shfl butterfly (offsets 1..8 stay inside
// each 16-lane half). redux.sync.add.f32 is NOT available on sm_103a.
__device__ __forceinline__ float group16_sum(float v) {
#pragma unroll
    for (int off = 1; off < 16; off <<= 1)
        v += __shfl_xor_sync(0xffffffffu, v, off);
    return v;
}

// ---------------------------------------------------------------------------
// Prep kernel: tiny GEMMs. 449 blocks x 512 threads, 4-way split-K.
//   r in [0,96)    : g_C[t=r]       = time_emb[r]   @ W3
//   r in [96,192)  : g_Wf[t=r-96]   = Wp[r-96]      @ W1
//   r in [192,448) : g_nodeS[r-192] = node_emb[..]  @ W2
//   r == 448       : g_bias         = bp @ W1 + bf
// ---------------------------------------------------------------------------
__global__ __launch_bounds__(512) void prep_kernel(
    const float* __restrict__ Wp,
    const float* __restrict__ bp,
    const float* __restrict__ Wf,
    const float* __restrict__ bf,
    const float* __restrict__ node_emb,
    const float* __restrict__ time_emb) {

    __shared__ float vsh[HH];
    __shared__ float partial[4][HH];

    const int r = blockIdx.x;
    const int k = threadIdx.x & (HH - 1);
    const int p = threadIdx.x >> 7;       // 0..3

    const float* __restrict__ v;
    const float* __restrict__ W;
    if (r < TT)                { v = time_emb + r * HH;        W = Wf + 2 * HH * HH; }
    else if (r < 2 * TT)       { v = Wp + (r - TT) * HH;       W = Wf; }
    else if (r < 2 * TT + NN)  { v = node_emb + (r - 2*TT)*HH; W = Wf + HH * HH; }
    else                       { v = bp;                       W = Wf; }

    if (threadIdx.x < HH) vsh[threadIdx.x] = v[threadIdx.x];
    __syncthreads();

    float acc = 0.f;
    const int h0 = p * 32;
#pragma unroll
    for (int hh = 0; hh < 32; hh++) {
        const int h = h0 + hh;
        acc += vsh[h] * W[h * HH + k];   // coalesced over k
    }
    partial[p][k] = acc;
    __syncthreads();

    if (threadIdx.x < HH) {
        float s = partial[0][k] + partial[1][k] + partial[2][k] + partial[3][k];
        if (r < TT)               g_C[r * HH + k] = s;
        else if (r < 2 * TT)      g_Wf[(r - TT) * HH + k] = s;
        else if (r < 2 * TT + NN) g_nodeS[(r - 2 * TT) * HH + k] = s;
        else                      g_bias[k] = s + bf[k];
    }
}

// ---------------------------------------------------------------------------
// GEMM-A kernel: g_A[pair,k] = bias[k] + nodeS[pair&255,k]
//                            + sum_t x[pair,t] * Wfused[t,k]
// 256 blocks x 256 threads, 16 pairs per block, register-blocked 8 pairs x
// 1 col per thread. x tile staged TRANSPOSED in smem so the inner loop is
// 1 coalesced LDG (Wf) + 2 broadcast LDS.128 + 8 FMA per t.
// Wf L2 traffic: 256 blocks x 48 KB = 12 MB total.
// ---------------------------------------------------------------------------
__global__ __launch_bounds__(256) void gemmA_kernel(const float* __restrict__ x) {
    __shared__ float xsT[TT][16];     // transposed x tile, 6 KB

    const int pair0 = blockIdx.x * 16;
    const int tid   = threadIdx.x;

    for (int idx = tid; idx < 16 * TT; idx += 256) {
        const int pl = idx / TT;
        const int t  = idx - pl * TT;
        xsT[t][pl] = x[(size_t)(pair0 + pl) * TT + t];
    }
    __syncthreads();

    const int k   = tid & (HH - 1);
    const int pl0 = (tid >> 7) * 8;   // 0 or 8

    float acc[8] = {0.f, 0.f, 0.f, 0.f, 0.f, 0.f, 0.f, 0.f};
#pragma unroll 4
    for (int t = 0; t < TT; t++) {
        const float wv = g_Wf[t * HH + k];
        const float4 xa = *reinterpret_cast<const float4*>(&xsT[t][pl0]);
        const float4 xb = *reinterpret_cast<const float4*>(&xsT[t][pl0 + 4]);
        acc[0] += wv * xa.x;  acc[1] += wv * xa.y;
        acc[2] += wv * xa.z;  acc[3] += wv * xa.w;
        acc[4] += wv * xb.x;  acc[5] += wv * xb.y;
        acc[6] += wv * xb.z;  acc[7] += wv * xb.w;
    }

    const float bias = __ldg(g_bias + k);
#pragma unroll
    for (int pl = 0; pl < 8; pl++) {
        const int pair = pair0 + pl0 + pl;
        const int n    = pair & (NN - 1);
        g_A[(size_t)pair * HH + k] = acc[pl] + bias + __ldg(g_nodeS + n * HH + k);
    }
}

// ---------------------------------------------------------------------------
// Main kernel: PURE STREAMING. 4096 blocks x 256 threads, one (b,n) pair
// per block. No shared memory, no __syncthreads. 16 lanes per row, 2 rows
// per warp per pass (6 passes = 96 rows). Lane il owns cols {4il..+4} and
// {64+4il..+4}; every STG.128 across the warp covers two contiguous 256B
// row segments. A slice + gamma/beta live in registers; C (48 KB) streams
// from L1. Row mean/var via 4-round shfl butterfly. Stores are __stcs
// (evict-first) so L2 is dedicated to the write stream.
// ---------------------------------------------------------------------------
__global__ __launch_bounds__(256, 4) void gpe_main_kernel(
    const float* __restrict__ gamma,
    const float* __restrict__ beta,
    float* __restrict__ out) {

    const int pair = blockIdx.x;
    const int tid  = threadIdx.x;
    const int w    = tid >> 5;
    const int l    = tid & 31;
    const int rgrp = l >> 4;
    const int il   = l & 15;
    const int col0 = 4 * il;
    const int r0   = w * 2 + rgrp;    // base row; passes add 16

    // Per-pair A slice (written by gemmA_kernel; 2 MB table, L2-hot)
    const float4 a0 = __ldg(reinterpret_cast<const float4*>(g_A + (size_t)pair * HH + col0));
    const float4 a1 = __ldg(reinterpret_cast<const float4*>(g_A + (size_t)pair * HH + 64 + col0));

    const float4 gg0 = __ldg(reinterpret_cast<const float4*>(gamma + col0));
    const float4 gg1 = __ldg(reinterpret_cast<const float4*>(gamma + 64 + col0));
    const float4 bb0 = __ldg(reinterpret_cast<const float4*>(beta + col0));
    const float4 bb1 = __ldg(reinterpret_cast<const float4*>(beta + 64 + col0));

    float* __restrict__ obase = out + (size_t)pair * (TT * HH);

#pragma unroll
    for (int pass = 0; pass < 6; pass++) {
        const int row = pass * 16 + r0;
        const float* __restrict__ crow = g_C + row * HH;
        const float4 c0 = __ldg(reinterpret_cast<const float4*>(crow + col0));
        const float4 c1 = __ldg(reinterpret_cast<const float4*>(crow + 64 + col0));

        float4 v0, v1;
        v0.x = fmaxf(a0.x + c0.x, 0.f);
        v0.y = fmaxf(a0.y + c0.y, 0.f);
        v0.z = fmaxf(a0.z + c0.z, 0.f);
        v0.w = fmaxf(a0.w + c0.w, 0.f);
        v1.x = fmaxf(a1.x + c1.x, 0.f);
        v1.y = fmaxf(a1.y + c1.y, 0.f);
        v1.z = fmaxf(a1.z + c1.z, 0.f);
        v1.w = fmaxf(a1.w + c1.w, 0.f);

        float s1 = v0.x + v0.y + v0.z + v0.w
                 + v1.x + v1.y + v1.z + v1.w;
        float s2 = v0.x * v0.x + v0.y * v0.y + v0.z * v0.z + v0.w * v0.w
                 + v1.x * v1.x + v1.y * v1.y + v1.z * v1.z + v1.w * v1.w;

        s1 = group16_sum(s1);
        s2 = group16_sum(s2);

        const float mean = s1 * (1.f / HH);
        const float var  = s2 * (1.f / HH) - mean * mean;
        const float rstd = rsqrtf(var + EPS);

        float4 o0, o1;
        o0.x = (v0.x - mean) * rstd * gg0.x + bb0.x;
        o0.y = (v0.y - mean) * rstd * gg0.y + bb0.y;
        o0.z = (v0.z - mean) * rstd * gg0.z + bb0.z;
        o0.w = (v0.w - mean) * rstd * gg0.w + bb0.w;
        o1.x = (v1.x - mean) * rstd * gg1.x + bb1.x;
        o1.y = (v1.y - mean) * rstd * gg1.y + bb1.y;
        o1.z = (v1.z - mean) * rstd * gg1.z + bb1.z;
        o1.w = (v1.w - mean) * rstd * gg1.w + bb1.w;

        float* __restrict__ orow = obase + row * HH;
        __stcs(reinterpret_cast<float4*>(orow + col0), o0);
        __stcs(reinterpret_cast<float4*>(orow + 64 + col0), o1);
    }
}

// ---------------------------------------------------------------------------
// Inputs: 0:x 1:Wp 2:bp 3:Wf 4:bf 5:gamma 6:beta 7:node_emb 8:time_emb
// ---------------------------------------------------------------------------
extern "C" void kernel_launch(void* const* d_in, const int* in_sizes, int n_in,
                              void* d_out, int out_size) {
    const float* x        = (const float*)d_in[0];
    const float* Wp       = (const float*)d_in[1];
    const float* bp       = (const float*)d_in[2];
    const float* Wf       = (const float*)d_in[3];
    const float* bf       = (const float*)d_in[4];
    const float* gamma    = (const float*)d_in[5];
    const float* beta     = (const float*)d_in[6];
    const float* node_emb = (const float*)d_in[7];
    const float* time_emb = (const float*)d_in[8];
    float* out = (float*)d_out;

    prep_kernel<<<2 * TT + NN + 1, 512>>>(Wp, bp, Wf, bf, node_emb, time_emb);
    gemmA_kernel<<<NPAIR / 16, 256>>>(x);
    gpe_main_kernel<<<NPAIR, 256>>>(gamma, beta, out);
}